// round 4
// baseline (speedup 1.0000x reference)
#include <cuda_runtime.h>

// Fixed problem shapes (from reference setup_inputs)
constexpr int B_    = 16;
constexpr int HS    = 640;
constexpr int WS    = 640;
constexpr int C_    = 3;
constexpr int NPIX  = 512 * 512;          // N = H_out*W_out = 262144 (2^18)
constexpr int NBITS = 18;                 // log2(NPIX)
constexpr int PPT   = 4;                  // pixels per thread

// L2-direct scalar gather (no L1 allocation for random picks)
__device__ __forceinline__ float ldg_cg(const float* p) {
    float v;
    asm volatile("ld.global.cg.f32 %0, [%1];" : "=f"(v) : "l"(p));
    return v;
}

__global__ __launch_bounds__(256, 8)   // force <=32 regs -> 64 warps/SM
void resample_nn_kernel(const float* __restrict__ idx,
                        const float* __restrict__ src,
                        float* __restrict__ out)
{
    const int t  = blockIdx.x * blockDim.x + threadIdx.x;
    const int g0 = t * PPT;                       // first pixel (global, b*N + n)
    const int b  = g0 >> NBITS;
    const int n0 = g0 & (NPIX - 1);

    // idx layout: [B, 2, N] -> rows at b*2N + n, cols at b*2N + N + n
    const float* idx_b = idx + (size_t)b * 2 * NPIX;
    const float4 r4 = __ldcs(reinterpret_cast<const float4*>(idx_b + n0));
    const float4 c4 = __ldcs(reinterpret_cast<const float4*>(idx_b + NPIX + n0));

    const float rs[PPT] = {r4.x, r4.y, r4.z, r4.w};
    const float cs[PPT] = {c4.x, c4.y, c4.z, c4.w};

    const float* __restrict__ sb = src + (size_t)b * HS * WS * C_;

    // Phase 1: all addresses + valid masks (pure ALU, no memory)
    const float* p[PPT];
    bool valid[PPT];
    #pragma unroll
    for (int i = 0; i < PPT; i++) {
        // trunc(x + 0.5) -> C int cast truncates toward zero, same semantics
        const int ir = (int)(rs[i] + 0.5f);
        const int ic = (int)(cs[i] + 0.5f);
        valid[i] = (ir >= 0) & (ic >= 0) & (ir < HS) & (ic < WS);
        const int irc = min(max(ir, 0), HS - 1);
        const int icc = min(max(ic, 0), WS - 1);
        p[i] = sb + (irc * WS + icc) * C_;
    }

    // Phase 2: all 12 gathers issued back-to-back (max MLP, L2-direct)
    float g[PPT * C_];
    #pragma unroll
    for (int i = 0; i < PPT; i++) {
        g[i * 3 + 0] = ldg_cg(p[i] + 0);
        g[i * 3 + 1] = ldg_cg(p[i] + 1);
        g[i * 3 + 2] = ldg_cg(p[i] + 2);
    }

    // Phase 3: mask + coalesced streaming stores
    float v[PPT * C_];
    #pragma unroll
    for (int i = 0; i < PPT; i++) {
        v[i * 3 + 0] = valid[i] ? g[i * 3 + 0] : 0.0f;
        v[i * 3 + 1] = valid[i] ? g[i * 3 + 1] : 0.0f;
        v[i * 3 + 2] = valid[i] ? g[i * 3 + 2] : 0.0f;
    }

    // out layout: [B, N, C]; 4 pixels * 3 ch = 12 floats = 3 x float4,
    // byte offset = g0*12, multiple of 48 -> 16B aligned.
    float4* o = reinterpret_cast<float4*>(out + (size_t)g0 * C_);
    __stcs(o + 0, make_float4(v[0], v[1], v[2],  v[3]));
    __stcs(o + 1, make_float4(v[4], v[5], v[6],  v[7]));
    __stcs(o + 2, make_float4(v[8], v[9], v[10], v[11]));
}

extern "C" void kernel_launch(void* const* d_in, const int* in_sizes, int n_in,
                              void* d_out, int out_size)
{
    const float* idx = (const float*)d_in[0];   // [B, 2, N] float32
    const float* src = (const float*)d_in[1];   // [B, Hs, Ws, C] float32
    float* out = (float*)d_out;                 // [B, H_out, W_out, C] float32

    const int total_pixels = B_ * NPIX;         // 4,194,304
    const int threads = total_pixels / PPT;     // 1,048,576
    const int block = 256;
    const int grid = threads / block;           // 4096

    resample_nn_kernel<<<grid, block>>>(idx, src, out);
}

// round 5
// speedup vs baseline: 1.3578x; 1.3578x over previous
#include <cuda_runtime.h>

// Fixed problem shapes (from reference setup_inputs)
constexpr int B_    = 16;
constexpr int HS    = 640;
constexpr int WS    = 640;
constexpr int C_    = 3;
constexpr int NPIX  = 512 * 512;          // N = H_out*W_out = 262144 (2^18)
constexpr int NBITS = 18;                 // log2(NPIX)
constexpr int TPX   = 4;                  // pixels per tile
constexpr int PPT   = 8;                  // pixels per thread (2 pipelined tiles)

struct Tile {
    int   off[TPX];    // byte offset into batch tile
    bool  valid[TPX];
};

__device__ __forceinline__ Tile make_tile(const float4& r4, const float4& c4) {
    Tile t;
    const float rs[TPX] = {r4.x, r4.y, r4.z, r4.w};
    const float cs[TPX] = {c4.x, c4.y, c4.z, c4.w};
    #pragma unroll
    for (int i = 0; i < TPX; i++) {
        // trunc(x + 0.5) -> C int cast truncates toward zero, same semantics
        const int ir = (int)(rs[i] + 0.5f);
        const int ic = (int)(cs[i] + 0.5f);
        t.valid[i] = (ir >= 0) & (ic >= 0) & (ir < HS) & (ic < WS);
        const int irc = min(max(ir, 0), HS - 1);
        const int icc = min(max(ic, 0), WS - 1);
        t.off[i] = (irc * WS + icc) * (C_ * 4);   // bytes
    }
    return t;
}

__device__ __forceinline__ void gather_tile(const char* __restrict__ sb,
                                            const Tile& t, float* g) {
    #pragma unroll
    for (int i = 0; i < TPX; i++) {
        const float* p = reinterpret_cast<const float*>(sb + t.off[i]);
        g[i * 3 + 0] = __ldg(p + 0);
        g[i * 3 + 1] = __ldg(p + 1);
        g[i * 3 + 2] = __ldg(p + 2);
    }
}

__device__ __forceinline__ void store_tile(float4* o, const Tile& t, const float* g) {
    float v[TPX * C_];
    #pragma unroll
    for (int i = 0; i < TPX; i++) {
        v[i * 3 + 0] = t.valid[i] ? g[i * 3 + 0] : 0.0f;
        v[i * 3 + 1] = t.valid[i] ? g[i * 3 + 1] : 0.0f;
        v[i * 3 + 2] = t.valid[i] ? g[i * 3 + 2] : 0.0f;
    }
    __stcs(o + 0, make_float4(v[0], v[1], v[2],  v[3]));
    __stcs(o + 1, make_float4(v[4], v[5], v[6],  v[7]));
    __stcs(o + 2, make_float4(v[8], v[9], v[10], v[11]));
}

__global__ __launch_bounds__(256)
void resample_nn_kernel(const float* __restrict__ idx,
                        const float* __restrict__ src,
                        float* __restrict__ out)
{
    const int t  = blockIdx.x * blockDim.x + threadIdx.x;
    const int g0 = t * PPT;                       // first pixel (global, b*N + n)
    const int b  = g0 >> NBITS;
    const int n0 = g0 & (NPIX - 1);

    // idx layout: [B, 2, N] -> rows at b*2N + n, cols at b*2N + N + n
    const float* idx_b = idx + (size_t)b * 2 * NPIX;
    const char* __restrict__ sb =
        reinterpret_cast<const char*>(src) + (size_t)b * HS * WS * C_ * sizeof(float);
    float4* o = reinterpret_cast<float4*>(out + (size_t)g0 * C_);

    // ---- software pipeline: overlap idx(DRAM) latency of tile B with ----
    // ---- gather(L2) latency of tile A                                 ----

    // stage 0: idx A
    const float4 rA = __ldcs(reinterpret_cast<const float4*>(idx_b + n0));
    const float4 cA = __ldcs(reinterpret_cast<const float4*>(idx_b + NPIX + n0));
    const Tile tA = make_tile(rA, cA);            // idx A regs die here

    // stage 1: idx B issued before gathers of A
    const float4 rB = __ldcs(reinterpret_cast<const float4*>(idx_b + n0 + 4));
    const float4 cB = __ldcs(reinterpret_cast<const float4*>(idx_b + NPIX + n0 + 4));

    float gA[TPX * C_];
    gather_tile(sb, tA, gA);                      // in flight while idx B lands

    const Tile tB = make_tile(rB, cB);

    float gB[TPX * C_];
    gather_tile(sb, tB, gB);                      // in flight while A is stored

    store_tile(o,     tA, gA);
    store_tile(o + 3, tB, gB);
}

extern "C" void kernel_launch(void* const* d_in, const int* in_sizes, int n_in,
                              void* d_out, int out_size)
{
    const float* idx = (const float*)d_in[0];   // [B, 2, N] float32
    const float* src = (const float*)d_in[1];   // [B, Hs, Ws, C] float32
    float* out = (float*)d_out;                 // [B, H_out, W_out, C] float32

    const int total_pixels = B_ * NPIX;         // 4,194,304
    const int threads = total_pixels / PPT;     // 524,288
    const int block = 256;
    const int grid = threads / block;           // 2048

    resample_nn_kernel<<<grid, block>>>(idx, src, out);
}

// round 6
// speedup vs baseline: 1.4992x; 1.1042x over previous
#include <cuda_runtime.h>

// Fixed problem shapes (from reference setup_inputs)
constexpr int B_    = 16;
constexpr int HS    = 640;
constexpr int WS    = 640;
constexpr int C_    = 3;
constexpr int NPIX  = 512 * 512;          // N = H_out*W_out = 262144 (2^18)
constexpr int NBITS = 18;                 // log2(NPIX)
constexpr int PPT   = 4;                  // pixels per grid-stride tile

constexpr int SMS       = 148;
constexpr int CTAS_PSM  = 8;
constexpr int GRID      = SMS * CTAS_PSM;     // 1184 -> exactly one wave
constexpr int BLOCK     = 256;
constexpr int NTILES    = (B_ * NPIX) / PPT;  // 1,048,576 tiles

// Predicated 16B gather: no BSSY/BSYNC, predicated-off lanes issue nothing.
__device__ __forceinline__ float4 ldg_f4_pred(const char* p, int doit) {
    float4 q = make_float4(0.f, 0.f, 0.f, 0.f);
    asm volatile(
        "{\n\t"
        ".reg .pred p;\n\t"
        "setp.ne.s32 p, %5, 0;\n\t"
        "@p ld.global.nc.v4.f32 {%0,%1,%2,%3}, [%4];\n\t"
        "}"
        : "+f"(q.x), "+f"(q.y), "+f"(q.z), "+f"(q.w)
        : "l"(p), "r"(doit));
    return q;
}

__global__ __launch_bounds__(BLOCK, CTAS_PSM)   // cap regs at 32
void resample_nn_kernel(const float* __restrict__ idx,
                        const float* __restrict__ src,
                        float* __restrict__ out)
{
    const int stride = GRID * BLOCK;

    for (int t = blockIdx.x * BLOCK + threadIdx.x; t < NTILES; t += stride) {
        const int g0 = t * PPT;                   // first pixel (global, b*N + n)
        const int b  = g0 >> NBITS;
        const int n0 = g0 & (NPIX - 1);

        // idx layout: [B, 2, N] -> rows at b*2N + n, cols at b*2N + N + n
        const float* idx_b = idx + (size_t)b * 2 * NPIX;
        const float4 r4 = __ldcs(reinterpret_cast<const float4*>(idx_b + n0));
        const float4 c4 = __ldcs(reinterpret_cast<const float4*>(idx_b + NPIX + n0));

        const float rs[PPT] = {r4.x, r4.y, r4.z, r4.w};
        const float cs[PPT] = {c4.x, c4.y, c4.z, c4.w};

        // byte base of this batch's source tile (16B aligned: 640*640*12 % 16 == 0)
        const char* __restrict__ sb =
            reinterpret_cast<const char*>(src) + (size_t)b * HS * WS * C_ * sizeof(float);

        float v[PPT * C_];
        #pragma unroll
        for (int i = 0; i < PPT; i++) {
            // trunc(x + 0.5) -> C int cast truncates toward zero, same semantics
            const int ir = (int)(rs[i] + 0.5f);
            const int ic = (int)(cs[i] + 0.5f);
            const bool valid = (ir >= 0) & (ic >= 0) & (ir < HS) & (ic < WS);
            const int irc = min(max(ir, 0), HS - 1);
            const int icc = min(max(ic, 0), WS - 1);

            const int pix  = irc * WS + icc;      // < 409600
            const int s    = pix * 12;            // byte offset of the 3 floats
            const int base = s & ~15;             // 16B-aligned slot
            const int k    = (s >> 2) & 3;        // word offset within slot (0..3)

            const float4 q0 = __ldg(reinterpret_cast<const float4*>(sb + base));
            // spill into next 16B slot only when k>=2; max read end == tile end (no OOB)
            const float4 q1 = ldg_f4_pred(sb + base + 16, k >= 2);

            // words[k], words[k+1], words[k+2] of {q0.x,q0.y,q0.z,q0.w,q1.x,q1.y}
            const float o0 = (k == 0) ? q0.x : (k == 1) ? q0.y : (k == 2) ? q0.z : q0.w;
            const float o1 = (k == 0) ? q0.y : (k == 1) ? q0.z : (k == 2) ? q0.w : q1.x;
            const float o2 = (k == 0) ? q0.z : (k == 1) ? q0.w : (k == 2) ? q1.x : q1.y;

            v[i * 3 + 0] = valid ? o0 : 0.0f;
            v[i * 3 + 1] = valid ? o1 : 0.0f;
            v[i * 3 + 2] = valid ? o2 : 0.0f;
        }

        // out layout: [B, N, C]; 4 pixels * 3 ch = 12 floats = 3 x float4,
        // byte offset = g0*12, multiple of 48 -> 16B aligned. Streaming stores.
        float4* o = reinterpret_cast<float4*>(out + (size_t)g0 * C_);
        __stcs(o + 0, make_float4(v[0], v[1], v[2],  v[3]));
        __stcs(o + 1, make_float4(v[4], v[5], v[6],  v[7]));
        __stcs(o + 2, make_float4(v[8], v[9], v[10], v[11]));
    }
}

extern "C" void kernel_launch(void* const* d_in, const int* in_sizes, int n_in,
                              void* d_out, int out_size)
{
    const float* idx = (const float*)d_in[0];   // [B, 2, N] float32
    const float* src = (const float*)d_in[1];   // [B, Hs, Ws, C] float32
    float* out = (float*)d_out;                 // [B, H_out, W_out, C] float32

    resample_nn_kernel<<<GRID, BLOCK>>>(idx, src, out);
}